// round 2
// baseline (speedup 1.0000x reference)
#include <cuda_runtime.h>

// Per-block partial sums: [block][8 values]. 4096 blocks max.
__device__ float g_part[4096 * 8];

static const int EPT = 4;        // elements per thread
static const int THREADS = 256;

__global__ __launch_bounds__(THREADS) void integrate_kernel(
    const float* __restrict__ nodal_values,  // (N_NODES, 8)
    const float* __restrict__ coords,        // (N_NODES, 2)
    const int*   __restrict__ elements,      // (E, 3)
    int n_elements)
{
    float acc[8];
#pragma unroll
    for (int v = 0; v < 8; v++) acc[v] = 0.0f;

    const int t = blockIdx.x * THREADS + threadIdx.x;
    const int base = t * EPT;

    if (base + EPT <= n_elements) {
        // Front-batched index load: 12 indices via 3x int4 (48B aligned for all t).
        const int4* ep = reinterpret_cast<const int4*>(elements + base * 3);
        const int4 w0 = ep[0];
        const int4 w1 = ep[1];
        const int4 w2 = ep[2];
        const int idx[12] = {w0.x, w0.y, w0.z, w0.w,
                             w1.x, w1.y, w1.z, w1.w,
                             w2.x, w2.y, w2.z, w2.w};

        // Front-batched coord gathers: 12 independent float2 loads in flight.
        float2 c[12];
#pragma unroll
        for (int j = 0; j < 12; j++)
            c[j] = *reinterpret_cast<const float2*>(coords + 2 * idx[j]);

        // Per-element scale s = det(J)/6 (3-pt symmetric rule: sum_q w_q N_q[n] = 1/6).
        float s[EPT];
#pragma unroll
        for (int e = 0; e < EPT; e++) {
            const float2 c0 = c[3 * e + 0];
            const float2 c1 = c[3 * e + 1];
            const float2 c2 = c[3 * e + 2];
            const float det = (c1.x - c0.x) * (c2.y - c0.y)
                            - (c1.y - c0.y) * (c2.x - c0.x);
            s[e] = det * (1.0f / 6.0f);
        }

        // Value gathers + accumulate. 6 independent float4 loads per element;
        // unrolled so ptxas can software-pipeline across elements.
#pragma unroll
        for (int e = 0; e < EPT; e++) {
            const float* p0 = nodal_values + 8 * idx[3 * e + 0];
            const float* p1 = nodal_values + 8 * idx[3 * e + 1];
            const float* p2 = nodal_values + 8 * idx[3 * e + 2];
            const float4 a0 = *reinterpret_cast<const float4*>(p0);
            const float4 b0 = *reinterpret_cast<const float4*>(p0 + 4);
            const float4 a1 = *reinterpret_cast<const float4*>(p1);
            const float4 b1 = *reinterpret_cast<const float4*>(p1 + 4);
            const float4 a2 = *reinterpret_cast<const float4*>(p2);
            const float4 b2 = *reinterpret_cast<const float4*>(p2 + 4);
            const float se = s[e];
            acc[0] += se * (a0.x + a1.x + a2.x);
            acc[1] += se * (a0.y + a1.y + a2.y);
            acc[2] += se * (a0.z + a1.z + a2.z);
            acc[3] += se * (a0.w + a1.w + a2.w);
            acc[4] += se * (b0.x + b1.x + b2.x);
            acc[5] += se * (b0.y + b1.y + b2.y);
            acc[6] += se * (b0.z + b1.z + b2.z);
            acc[7] += se * (b0.w + b1.w + b2.w);
        }
    } else {
        // Tail: per-element guarded scalar path.
        for (int e = base; e < n_elements; e++) {
            const int i0 = elements[3 * e + 0];
            const int i1 = elements[3 * e + 1];
            const int i2 = elements[3 * e + 2];
            const float2 c0 = *reinterpret_cast<const float2*>(coords + 2 * i0);
            const float2 c1 = *reinterpret_cast<const float2*>(coords + 2 * i1);
            const float2 c2 = *reinterpret_cast<const float2*>(coords + 2 * i2);
            const float det = (c1.x - c0.x) * (c2.y - c0.y)
                            - (c1.y - c0.y) * (c2.x - c0.x);
            const float se = det * (1.0f / 6.0f);
            const float* p0 = nodal_values + 8 * i0;
            const float* p1 = nodal_values + 8 * i1;
            const float* p2 = nodal_values + 8 * i2;
#pragma unroll
            for (int v = 0; v < 8; v++)
                acc[v] += se * (p0[v] + p1[v] + p2[v]);
        }
    }

    // Block reduction: warp shuffle, then cross-warp via smem.
#pragma unroll
    for (int v = 0; v < 8; v++) {
#pragma unroll
        for (int off = 16; off > 0; off >>= 1)
            acc[v] += __shfl_down_sync(0xFFFFFFFFu, acc[v], off);
    }

    __shared__ float sred[8][8];  // [warp][value]
    const int warp = threadIdx.x >> 5;
    const int lane = threadIdx.x & 31;
    if (lane == 0) {
#pragma unroll
        for (int v = 0; v < 8; v++) sred[warp][v] = acc[v];
    }
    __syncthreads();

    if (threadIdx.x < 8) {
        float sum = 0.0f;
#pragma unroll
        for (int w = 0; w < 8; w++) sum += sred[w][threadIdx.x];
        g_part[blockIdx.x * 8 + threadIdx.x] = sum;
    }
}

// Final reduction: warp w sums value w across all block partials.
__global__ __launch_bounds__(256) void finalize_kernel(float* __restrict__ out, int nblocks) {
    const int warp = threadIdx.x >> 5;  // value index 0..7
    const int lane = threadIdx.x & 31;
    double sum = 0.0;
    for (int b = lane; b < nblocks; b += 32)
        sum += (double)g_part[b * 8 + warp];
#pragma unroll
    for (int off = 16; off > 0; off >>= 1)
        sum += __shfl_down_sync(0xFFFFFFFFu, sum, off);
    if (lane == 0) out[warp] = (float)sum;
}

extern "C" void kernel_launch(void* const* d_in, const int* in_sizes, int n_in,
                              void* d_out, int out_size) {
    const float* nodal_values = (const float*)d_in[0];
    const float* coords       = (const float*)d_in[1];
    const int*   elements     = (const int*)d_in[2];
    float* out = (float*)d_out;

    const int n_elements = in_sizes[2] / 3;
    const int n_threads = (n_elements + EPT - 1) / EPT;
    const int blocks = (n_threads + THREADS - 1) / THREADS;  // 1954 for E=2M

    integrate_kernel<<<blocks, THREADS>>>(nodal_values, coords, elements, n_elements);
    finalize_kernel<<<1, 256>>>(out, blocks);
}

// round 3
// speedup vs baseline: 1.7769x; 1.7769x over previous
#include <cuda_runtime.h>

// Scatter target: per-node weight accumulator. Zero-initialized at module load;
// phase 2 re-zeroes it after consuming, so every replay starts from zeros.
__device__ float g_w[4 * 1024 * 1024];
__device__ double g_acc[8];
__device__ unsigned int g_count;

// ---------------- Phase 1: per-element det(J)/6 scattered to node weights ----
__global__ __launch_bounds__(256) void phase1_kernel(
    const float* __restrict__ coords,    // (N_NODES, 2)
    const int*   __restrict__ elements,  // (E, 3)
    int n_elements)
{
    const int stride = gridDim.x * blockDim.x;
    for (int e = blockIdx.x * blockDim.x + threadIdx.x; e < n_elements; e += stride) {
        const int i0 = elements[3 * e + 0];
        const int i1 = elements[3 * e + 1];
        const int i2 = elements[3 * e + 2];

        const float2 c0 = *reinterpret_cast<const float2*>(coords + 2 * i0);
        const float2 c1 = *reinterpret_cast<const float2*>(coords + 2 * i1);
        const float2 c2 = *reinterpret_cast<const float2*>(coords + 2 * i2);

        // det(J) for Tri3; 3-pt symmetric rule gives sum_q w_q N_q[n] = 1/6 per node.
        const float det = (c1.x - c0.x) * (c2.y - c0.y)
                        - (c1.y - c0.y) * (c2.x - c0.x);
        const float s = det * (1.0f / 6.0f);

        atomicAdd(&g_w[i0], s);   // compiles to REDG.F32 (no return use)
        atomicAdd(&g_w[i1], s);
        atomicAdd(&g_w[i2], s);
    }
}

// ---------------- Phase 2: dense dot product  out[v] = sum_n w[n]*vals[n][v] --
__global__ __launch_bounds__(256) void phase2_kernel(
    const float* __restrict__ nodal_values,  // (N_NODES, 8)
    float* __restrict__ out,
    int n_nodes, int nblocks)
{
    float acc[8];
#pragma unroll
    for (int v = 0; v < 8; v++) acc[v] = 0.0f;

    const int stride = gridDim.x * blockDim.x;
    for (int n = blockIdx.x * blockDim.x + threadIdx.x; n < n_nodes; n += stride) {
        const float wn = g_w[n];
        g_w[n] = 0.0f;  // reset for next replay (this thread owns this slot)
        const float4 a = *reinterpret_cast<const float4*>(nodal_values + 8 * n);
        const float4 b = *reinterpret_cast<const float4*>(nodal_values + 8 * n + 4);
        acc[0] += wn * a.x;  acc[1] += wn * a.y;
        acc[2] += wn * a.z;  acc[3] += wn * a.w;
        acc[4] += wn * b.x;  acc[5] += wn * b.y;
        acc[6] += wn * b.z;  acc[7] += wn * b.w;
    }

    // Warp reduce, then cross-warp reduce in smem.
#pragma unroll
    for (int v = 0; v < 8; v++) {
#pragma unroll
        for (int off = 16; off > 0; off >>= 1)
            acc[v] += __shfl_down_sync(0xFFFFFFFFu, acc[v], off);
    }

    __shared__ float sred[8][8];
    const int warp = threadIdx.x >> 5;
    const int lane = threadIdx.x & 31;
    if (lane == 0) {
#pragma unroll
        for (int v = 0; v < 8; v++) sred[warp][v] = acc[v];
    }
    __syncthreads();

    if (threadIdx.x < 8) {
        float sum = 0.0f;
#pragma unroll
        for (int w = 0; w < 8; w++) sum += sred[w][threadIdx.x];
        atomicAdd(&g_acc[threadIdx.x], (double)sum);
    }

    // Last-block-done: fused finalize + state reset (graph-replay deterministic).
    __shared__ bool is_last;
    __threadfence();
    if (threadIdx.x == 0) {
        unsigned int old = atomicInc(&g_count, (unsigned int)(nblocks - 1));
        is_last = (old == (unsigned int)(nblocks - 1));  // counter auto-wraps to 0
    }
    __syncthreads();

    if (is_last && threadIdx.x < 8) {
        const double val = atomicAdd(&g_acc[threadIdx.x], 0.0);  // coherent read
        out[threadIdx.x] = (float)val;
        g_acc[threadIdx.x] = 0.0;  // reset for next replay
    }
}

extern "C" void kernel_launch(void* const* d_in, const int* in_sizes, int n_in,
                              void* d_out, int out_size) {
    const float* nodal_values = (const float*)d_in[0];
    const float* coords       = (const float*)d_in[1];
    const int*   elements     = (const int*)d_in[2];
    float* out = (float*)d_out;

    const int n_elements = in_sizes[2] / 3;
    const int n_nodes    = in_sizes[1] / 2;

    const int p1_blocks = 2048;
    phase1_kernel<<<p1_blocks, 256>>>(coords, elements, n_elements);

    const int p2_blocks = 1024;
    phase2_kernel<<<p2_blocks, 256>>>(nodal_values, out, n_nodes, p2_blocks);
}

// round 4
// speedup vs baseline: 1.9103x; 1.0751x over previous
#include <cuda_runtime.h>

// Per-node weight accumulator. Zero at module load; phase 2 re-zeroes after
// consuming, so every graph replay starts from zeros.
__device__ float g_w[4 * 1024 * 1024];
__device__ double g_acc[8];
__device__ unsigned int g_count;

// ---------------- Phase 1: per-element det(J)/6 scattered to node weights ----
__global__ __launch_bounds__(256) void phase1_kernel(
    const float* __restrict__ coords,    // (N_NODES, 2)
    const int*   __restrict__ elements,  // (E, 3)
    int n_elements)
{
    const int e = blockIdx.x * 256 + threadIdx.x;
    if (e >= n_elements) return;

    const int i0 = elements[3 * e + 0];
    const int i1 = elements[3 * e + 1];
    const int i2 = elements[3 * e + 2];

    const float2 c0 = *reinterpret_cast<const float2*>(coords + 2 * i0);
    const float2 c1 = *reinterpret_cast<const float2*>(coords + 2 * i1);
    const float2 c2 = *reinterpret_cast<const float2*>(coords + 2 * i2);

    // det(J) for Tri3; 3-pt symmetric rule gives sum_q w_q N_q[n] = 1/6 per node.
    const float det = (c1.x - c0.x) * (c2.y - c0.y)
                    - (c1.y - c0.y) * (c2.x - c0.x);
    const float s = det * (1.0f / 6.0f);

    atomicAdd(&g_w[i0], s);   // REDG.F32, no return
    atomicAdd(&g_w[i1], s);
    atomicAdd(&g_w[i2], s);
}

// ---------------- Phase 2: dense dot  out[v] = sum_n w[n]*vals[n][v] ---------
// nodal_values viewed as 2*N float4s. Even float4 j -> v0..3 of node j/2,
// odd j -> v4..7. Thread parity == j parity (stride is even), so each thread
// always accumulates the same 4-value group; warp reduce preserves parity.
static const int P2_UNROLL = 4;

__global__ __launch_bounds__(256) void phase2_kernel(
    const float4* __restrict__ vals4,  // 2*N_NODES float4s
    float* __restrict__ out,
    int n_f4, int nblocks)
{
    const int T = nblocks * 256;  // total threads (even)
    const int t = blockIdx.x * 256 + threadIdx.x;

    // Front-batched guarded loads: up to 8 independent loads in flight.
    float  wreg[P2_UNROLL];
    float4 vreg[P2_UNROLL];
#pragma unroll
    for (int k = 0; k < P2_UNROLL; k++) {
        const int j = t + k * T;
        if (j < n_f4) {
            wreg[k] = g_w[j >> 1];
            vreg[k] = vals4[j];
        } else {
            wreg[k] = 0.0f;
            vreg[k] = make_float4(0.f, 0.f, 0.f, 0.f);
        }
    }

    // Zero w for next replay: even threads own even j = 2n -> every node once.
    if ((t & 1) == 0) {
#pragma unroll
        for (int k = 0; k < P2_UNROLL; k++) {
            const int j = t + k * T;
            if (j < n_f4) g_w[j >> 1] = 0.0f;
        }
    }

    float4 acc = make_float4(0.f, 0.f, 0.f, 0.f);
#pragma unroll
    for (int k = 0; k < P2_UNROLL; k++) {
        acc.x += wreg[k] * vreg[k].x;
        acc.y += wreg[k] * vreg[k].y;
        acc.z += wreg[k] * vreg[k].z;
        acc.w += wreg[k] * vreg[k].w;
    }

    // Parity-preserving warp reduction: xor offsets 16,8,4,2 combine only
    // same-parity lanes. Lane0 ends with sum of even lanes (v0-3),
    // lane1 with sum of odd lanes (v4-7).
#pragma unroll
    for (int off = 16; off >= 2; off >>= 1) {
        acc.x += __shfl_xor_sync(0xFFFFFFFFu, acc.x, off);
        acc.y += __shfl_xor_sync(0xFFFFFFFFu, acc.y, off);
        acc.z += __shfl_xor_sync(0xFFFFFFFFu, acc.z, off);
        acc.w += __shfl_xor_sync(0xFFFFFFFFu, acc.w, off);
    }

    __shared__ float4 sred[8][2];  // [warp][parity]
    const int warp = threadIdx.x >> 5;
    const int lane = threadIdx.x & 31;
    if (lane < 2) sred[warp][lane] = acc;
    __syncthreads();

    if (threadIdx.x < 2) {
        const int p = threadIdx.x;  // 0 -> v0-3, 1 -> v4-7
        float4 sum = make_float4(0.f, 0.f, 0.f, 0.f);
#pragma unroll
        for (int w = 0; w < 8; w++) {
            sum.x += sred[w][p].x;  sum.y += sred[w][p].y;
            sum.z += sred[w][p].z;  sum.w += sred[w][p].w;
        }
        atomicAdd(&g_acc[4 * p + 0], (double)sum.x);
        atomicAdd(&g_acc[4 * p + 1], (double)sum.y);
        atomicAdd(&g_acc[4 * p + 2], (double)sum.z);
        atomicAdd(&g_acc[4 * p + 3], (double)sum.w);
    }

    // Last-block-done: fused finalize + state reset.
    __shared__ bool is_last;
    __threadfence();
    if (threadIdx.x == 0) {
        unsigned int old = atomicInc(&g_count, (unsigned int)(nblocks - 1));
        is_last = (old == (unsigned int)(nblocks - 1));
    }
    __syncthreads();

    if (is_last && threadIdx.x < 8) {
        const double val = atomicAdd(&g_acc[threadIdx.x], 0.0);
        out[threadIdx.x] = (float)val;
        g_acc[threadIdx.x] = 0.0;
    }
}

extern "C" void kernel_launch(void* const* d_in, const int* in_sizes, int n_in,
                              void* d_out, int out_size) {
    const float* nodal_values = (const float*)d_in[0];
    const float* coords       = (const float*)d_in[1];
    const int*   elements     = (const int*)d_in[2];
    float* out = (float*)d_out;

    const int n_elements = in_sizes[2] / 3;
    const int n_nodes    = in_sizes[1] / 2;
    const int n_f4       = n_nodes * 2;

    const int p1_blocks = (n_elements + 255) / 256;
    phase1_kernel<<<p1_blocks, 256>>>(coords, elements, n_elements);

    const int p2_blocks = (n_f4 + 256 * P2_UNROLL - 1) / (256 * P2_UNROLL);
    phase2_kernel<<<p2_blocks, 256>>>(
        reinterpret_cast<const float4*>(nodal_values), out, n_f4, p2_blocks);
}

// round 5
// speedup vs baseline: 1.9506x; 1.0211x over previous
#include <cuda_runtime.h>

// Per-node weight accumulator. Zero at module load; phase 2 re-zeroes after
// consuming, so every graph replay starts from zeros.
__device__ float g_w[4 * 1024 * 1024];
__device__ double g_acc[8];
__device__ unsigned int g_count;

static const int EPT = 4;  // elements per thread in phase 1

// ---------------- Phase 1: per-element det(J)/6 scattered to node weights ----
__global__ __launch_bounds__(256) void phase1_kernel(
    const float* __restrict__ coords,    // (N_NODES, 2)
    const int*   __restrict__ elements,  // (E, 3)
    int n_elements)
{
    const int t = blockIdx.x * 256 + threadIdx.x;
    const int base = t * EPT;

    if (base + EPT <= n_elements) {
        // 12 indices via 3x int4 (48B-aligned for all t).
        const int4* ep = reinterpret_cast<const int4*>(elements + base * 3);
        const int4 w0 = ep[0];
        const int4 w1 = ep[1];
        const int4 w2 = ep[2];
        const int idx[12] = {w0.x, w0.y, w0.z, w0.w,
                             w1.x, w1.y, w1.z, w1.w,
                             w2.x, w2.y, w2.z, w2.w};

        // 12 independent coord gathers in flight.
        float2 c[12];
#pragma unroll
        for (int j = 0; j < 12; j++)
            c[j] = *reinterpret_cast<const float2*>(coords + 2 * idx[j]);

        // s_e = det(J)/6 (3-pt symmetric rule: sum_q w_q N_q[n] = 1/6 per node).
        float s[EPT];
#pragma unroll
        for (int e = 0; e < EPT; e++) {
            const float2 c0 = c[3 * e + 0];
            const float2 c1 = c[3 * e + 1];
            const float2 c2 = c[3 * e + 2];
            const float det = (c1.x - c0.x) * (c2.y - c0.y)
                            - (c1.y - c0.y) * (c2.x - c0.x);
            s[e] = det * (1.0f / 6.0f);
        }

        // 12 REDG.F32 scatters.
#pragma unroll
        for (int e = 0; e < EPT; e++) {
            atomicAdd(&g_w[idx[3 * e + 0]], s[e]);
            atomicAdd(&g_w[idx[3 * e + 1]], s[e]);
            atomicAdd(&g_w[idx[3 * e + 2]], s[e]);
        }
    } else {
        for (int e = base; e < n_elements; e++) {
            const int i0 = elements[3 * e + 0];
            const int i1 = elements[3 * e + 1];
            const int i2 = elements[3 * e + 2];
            const float2 c0 = *reinterpret_cast<const float2*>(coords + 2 * i0);
            const float2 c1 = *reinterpret_cast<const float2*>(coords + 2 * i1);
            const float2 c2 = *reinterpret_cast<const float2*>(coords + 2 * i2);
            const float det = (c1.x - c0.x) * (c2.y - c0.y)
                            - (c1.y - c0.y) * (c2.x - c0.x);
            const float se = det * (1.0f / 6.0f);
            atomicAdd(&g_w[i0], se);
            atomicAdd(&g_w[i1], se);
            atomicAdd(&g_w[i2], se);
        }
    }
}

// ---------------- Phase 2: dense dot  out[v] = sum_n w[n]*vals[n][v] ---------
// nodal_values viewed as 2*N float4s. Even float4 j -> v0..3 of node j/2,
// odd j -> v4..7. Thread parity == j parity (stride is even), so each thread
// always accumulates the same 4-value group; xor-reduce preserves parity.
static const int P2_UNROLL = 8;

__global__ __launch_bounds__(256) void phase2_kernel(
    const float4* __restrict__ vals4,  // 2*N_NODES float4s
    float* __restrict__ out,
    int n_f4, int nblocks)
{
    const int T = nblocks * 256;  // total threads (even)
    const int t = blockIdx.x * 256 + threadIdx.x;

    // Front-batched guarded loads: up to 16 independent loads in flight.
    float  wreg[P2_UNROLL];
    float4 vreg[P2_UNROLL];
#pragma unroll
    for (int k = 0; k < P2_UNROLL; k++) {
        const int j = t + k * T;
        if (j < n_f4) {
            wreg[k] = g_w[j >> 1];
            vreg[k] = vals4[j];
        } else {
            wreg[k] = 0.0f;
            vreg[k] = make_float4(0.f, 0.f, 0.f, 0.f);
        }
    }

    // Zero w for next replay: even threads own even j = 2n -> every node once.
    if ((t & 1) == 0) {
#pragma unroll
        for (int k = 0; k < P2_UNROLL; k++) {
            const int j = t + k * T;
            if (j < n_f4) g_w[j >> 1] = 0.0f;
        }
    }

    float4 acc = make_float4(0.f, 0.f, 0.f, 0.f);
#pragma unroll
    for (int k = 0; k < P2_UNROLL; k++) {
        acc.x += wreg[k] * vreg[k].x;
        acc.y += wreg[k] * vreg[k].y;
        acc.z += wreg[k] * vreg[k].z;
        acc.w += wreg[k] * vreg[k].w;
    }

    // Parity-preserving xor reduction (offsets 16,8,4,2): lane0 = even lanes
    // (v0-3), lane1 = odd lanes (v4-7).
#pragma unroll
    for (int off = 16; off >= 2; off >>= 1) {
        acc.x += __shfl_xor_sync(0xFFFFFFFFu, acc.x, off);
        acc.y += __shfl_xor_sync(0xFFFFFFFFu, acc.y, off);
        acc.z += __shfl_xor_sync(0xFFFFFFFFu, acc.z, off);
        acc.w += __shfl_xor_sync(0xFFFFFFFFu, acc.w, off);
    }

    __shared__ float4 sred[8][2];  // [warp][parity]
    const int warp = threadIdx.x >> 5;
    const int lane = threadIdx.x & 31;
    if (lane < 2) sred[warp][lane] = acc;
    __syncthreads();

    if (threadIdx.x < 2) {
        const int p = threadIdx.x;  // 0 -> v0-3, 1 -> v4-7
        float4 sum = make_float4(0.f, 0.f, 0.f, 0.f);
#pragma unroll
        for (int w = 0; w < 8; w++) {
            sum.x += sred[w][p].x;  sum.y += sred[w][p].y;
            sum.z += sred[w][p].z;  sum.w += sred[w][p].w;
        }
        atomicAdd(&g_acc[4 * p + 0], (double)sum.x);
        atomicAdd(&g_acc[4 * p + 1], (double)sum.y);
        atomicAdd(&g_acc[4 * p + 2], (double)sum.z);
        atomicAdd(&g_acc[4 * p + 3], (double)sum.w);
    }

    // Last-block-done: fused finalize + state reset.
    __shared__ bool is_last;
    __threadfence();
    if (threadIdx.x == 0) {
        unsigned int old = atomicInc(&g_count, (unsigned int)(nblocks - 1));
        is_last = (old == (unsigned int)(nblocks - 1));
    }
    __syncthreads();

    if (is_last && threadIdx.x < 8) {
        const double val = atomicAdd(&g_acc[threadIdx.x], 0.0);
        out[threadIdx.x] = (float)val;
        g_acc[threadIdx.x] = 0.0;
    }
}

extern "C" void kernel_launch(void* const* d_in, const int* in_sizes, int n_in,
                              void* d_out, int out_size) {
    const float* nodal_values = (const float*)d_in[0];
    const float* coords       = (const float*)d_in[1];
    const int*   elements     = (const int*)d_in[2];
    float* out = (float*)d_out;

    const int n_elements = in_sizes[2] / 3;
    const int n_nodes    = in_sizes[1] / 2;
    const int n_f4       = n_nodes * 2;

    const int p1_threads = (n_elements + EPT - 1) / EPT;
    const int p1_blocks = (p1_threads + 255) / 256;  // 1954 for E=2M
    phase1_kernel<<<p1_blocks, 256>>>(coords, elements, n_elements);

    const int p2_blocks = (n_f4 + 256 * P2_UNROLL - 1) / (256 * P2_UNROLL);  // 977
    phase2_kernel<<<p2_blocks, 256>>>(
        reinterpret_cast<const float4*>(nodal_values), out, n_f4, p2_blocks);
}